// round 11
// baseline (speedup 1.0000x reference)
#include <cuda_runtime.h>
#include <cuda_fp16.h>

#define N_NODES  50000
#define N_EDGES  1600000
#define BATCH    4
#define T_STEPS  50
#define DT_CONST 0.02f

#define NTHREADS 512
#define TN       (T_STEPS * N_NODES)
#define QPC      (NTHREADS / 4)     // 128 quads per CTA
#define MAXCTA   512                // scan width bound; >= 3*160 SMs
#define MAXQ     (MAXCTA * QPC)
#define ECAP     4096               // smem edge capacity per CTA (16KB packed)

// ---------------- device scratch (static, no allocation) ----------------
__device__ int      g_deg[N_NODES];
__device__ int      g_rowptr[N_NODES + 1];
__device__ int      g_cursor[N_NODES];
__device__ int      g_rowLo[MAXQ + 1];      // quad -> first row of its contiguous range
__device__ unsigned g_wp[N_EDGES];          // packed edge: (src<<16) | fp16(w)
__device__ float2   g_ab[N_NODES];          // {alpha, bias}
__device__ float    g_Vf[N_NODES * 4];      // membrane potential [n][b]
__device__ float4   g_R[2][N_NODES];        // double-buffered relu(v) fp32
__device__ int      g_blockSum[MAXCTA];
__device__ unsigned g_bar;

// ---------------- grid barrier (monotone counter, reset by init kernel) ----------------
__device__ __forceinline__ void grid_bar(unsigned k) {
    __syncthreads();
    if (threadIdx.x == 0) {
        __threadfence();
        atomicAdd(&g_bar, 1u);
        const unsigned target = k * gridDim.x;
        while (*(volatile unsigned*)&g_bar < target) { }
    }
    __syncthreads();
}

// ---------------- block-wide inclusive scan (Kogge-Stone in smem) ----------------
__device__ int block_scan_incl(int v) {
    __shared__ int ss[NTHREADS];
    const int tid = threadIdx.x;
    ss[tid] = v;
    __syncthreads();
#pragma unroll
    for (int off = 1; off < NTHREADS; off <<= 1) {
        int t = 0;
        if (tid >= off) t = ss[tid - off];
        __syncthreads();
        if (tid >= off) ss[tid] += t;
        __syncthreads();
    }
    return ss[tid];
}

__device__ __forceinline__ int quad_of_offset(int off, int nquads) {
    return (int)(((long long)off * nquads) / N_EDGES);
}

// coalesced transpose-copy of one time plane: out[b][t][n] = R[n].b for this CTA's chunk
__device__ __forceinline__ void copy_plane(int t, const float4* __restrict__ Rb,
                                           float* __restrict__ out,
                                           int cbase, int chunk, int tid) {
    const int n = cbase + tid;
    if (tid < chunk && n < N_NODES) {
        float4 rv = __ldcg(&Rb[n]);          // other-SM data: L2 (stable this phase)
        float* ot = out + t * N_NODES + n;
        ot[0 * TN] = rv.x;
        ot[1 * TN] = rv.y;
        ot[2 * TN] = rv.z;
        ot[3 * TN] = rv.w;
    }
}

// ---------------- init kernel: reset per-launch mutable state ----------------
__global__ void init_kernel() {
    int i = blockIdx.x * blockDim.x + threadIdx.x;
    if (i == 0) g_bar = 0u;
    for (int n = i; n < N_NODES; n += gridDim.x * blockDim.x) g_deg[n] = 0;
}

// ---------------- fallback hot loop (global edges; same barrier count as main) ----------------
__device__ __noinline__ void run_steps_fallback(
    int rowA, int rowB, int q, unsigned qmask,
    const float* __restrict__ x, float* __restrict__ out,
    int cbase, int chunk, int tid, unsigned& barK)
{
    for (int t = 0; t < T_STEPS; t++) {
        const float4* __restrict__ Rc  = g_R[t & 1];
        float*        __restrict__ Rnf = (float*)(g_R[(t + 1) & 1]);
        const float*  __restrict__ xt  = x + t * N_NODES;

        if (t > 0) copy_plane(t - 1, Rc, out, cbase, chunk, tid);

        for (int r = rowA; r < rowB; ++r) {
            const int beg = g_rowptr[r];
            const int end = g_rowptr[r + 1];
            const float xv = __ldcg(xt + q * TN + r);
            float a0 = 0.f, a1 = 0.f, a2 = 0.f, a3 = 0.f;
            for (int e = beg + q; e < end; e += 4) {
                unsigned u = __ldg(&g_wp[e]);
                float w = __half2float(__ushort_as_half((unsigned short)(u & 0xFFFFu)));
                float4 rv = __ldcg(&Rc[u >> 16]);
                a0 = fmaf(w, rv.x, a0); a1 = fmaf(w, rv.y, a1);
                a2 = fmaf(w, rv.z, a2); a3 = fmaf(w, rv.w, a3);
            }
#pragma unroll
            for (int off = 1; off < 4; off <<= 1) {
                a0 += __shfl_xor_sync(qmask, a0, off);
                a1 += __shfl_xor_sync(qmask, a1, off);
                a2 += __shfl_xor_sync(qmask, a2, off);
                a3 += __shfl_xor_sync(qmask, a3, off);
            }
            float acc = (q == 0) ? a0 : (q == 1) ? a1 : (q == 2) ? a2 : a3;
            float2 ab = g_ab[r];
            float  v  = g_Vf[4 * r + q];
            v = fmaf(ab.x, (ab.y - v) + (acc + xv), v);
            g_Vf[4 * r + q] = v;
            Rnf[4 * r + q] = fmaxf(v, 0.0f);
        }
        if (t != T_STEPS - 1) grid_bar(++barK);
    }
    grid_bar(++barK);
    copy_plane(T_STEPS - 1, g_R[T_STEPS & 1], out, cbase, chunk, tid);
}

// ---------------- main persistent kernel ----------------
__global__ void __launch_bounds__(NTHREADS, 3) net_kernel(
    const float* __restrict__ x,       // [B, T, N]
    const float* __restrict__ bias,    // [N]
    const float* __restrict__ tconst,  // [N]
    const float* __restrict__ sign,    // [E]
    const float* __restrict__ cnt,     // [E]
    const float* __restrict__ strg,    // [E]
    const int*   __restrict__ src,     // [E]
    const int*   __restrict__ tgt,     // [E]
    float*       __restrict__ out,     // [B, T, N]
    int chunk)
{
    __shared__ unsigned s_ws[ECAP];    // packed edge slice (16KB)

    const int tid   = threadIdx.x;
    const int bid   = blockIdx.x;
    const int ncta  = gridDim.x;
    const int gtid  = bid * NTHREADS + tid;
    const int nthr  = ncta * NTHREADS;
    const int nquads = ncta * QPC;
    const int cbase = bid * chunk;
    unsigned barK = 0;

    // ---- Pass A: degree histogram over targets ----
    for (int e = gtid; e < N_EDGES; e += nthr)
        atomicAdd(&g_deg[tgt[e]], 1);
    grid_bar(++barK);

    // ---- Pass B1: per-CTA chunk sums ----
    {
        const int n = cbase + tid;
        int v = (tid < chunk && n < N_NODES) ? g_deg[n] : 0;
        int incl = block_scan_incl(v);
        if (tid == NTHREADS - 1) g_blockSum[bid] = incl;
    }
    grid_bar(++barK);

    // ---- Pass B2: CTA0 exclusive-scans the block sums ----
    if (bid == 0) {
        int v = (tid < ncta) ? g_blockSum[tid] : 0;
        int incl = block_scan_incl(v);
        if (tid < ncta) g_blockSum[tid] = incl - v;
    }
    grid_bar(++barK);

    // ---- Pass B3: per-chunk exclusive scan -> row_ptr & cursor ----
    {
        const int n = cbase + tid;
        int v = (tid < chunk && n < N_NODES) ? g_deg[n] : 0;
        int incl = block_scan_incl(v);
        if (tid < chunk && n < N_NODES) {
            int rp = g_blockSum[bid] + incl - v;
            g_rowptr[n] = rp;
            g_cursor[n] = rp;
        }
        if (gtid == 0) g_rowptr[N_NODES] = N_EDGES;
    }
    grid_bar(++barK);

    // ---- Pass C: scatter packed edges into CSR slots ----
    for (int e = gtid; e < N_EDGES; e += nthr) {
        float w = sign[e] * fmaxf(cnt[e], 0.0f) * fmaxf(strg[e], 0.0f);
        int  t = tgt[e];
        int  p = atomicAdd(&g_cursor[t], 1);
        unsigned hw = (unsigned)__half_as_ushort(__float2half_rn(w));
        g_wp[p] = ((unsigned)src[e] << 16) | hw;
    }

    // ---- Edge-balanced quad->row-range partition ----
    for (int r = gtid; r <= N_NODES; r += nthr) {
        int a, b;
        if (r == N_NODES) {
            a = min(quad_of_offset(g_rowptr[N_NODES - 1], nquads), nquads - 1) + 1;
            b = nquads;
        } else {
            b = min(quad_of_offset(g_rowptr[r], nquads), nquads - 1);
            a = (r == 0) ? 0 : min(quad_of_offset(g_rowptr[r - 1], nquads), nquads - 1) + 1;
        }
        for (int qq = a; qq <= b; qq++) g_rowLo[qq] = r;
    }

    // ---- Pass D: node state init ----
    for (int n = gtid; n < N_NODES; n += nthr) {
        float b   = bias[n];
        float tau = fmaxf(tconst[n], DT_CONST);
        g_ab[n] = make_float2(DT_CONST / tau, b);
        float r = fmaxf(b, 0.0f);
        g_Vf[4 * n + 0] = b; g_Vf[4 * n + 1] = b;
        g_Vf[4 * n + 2] = b; g_Vf[4 * n + 3] = b;
        g_R[0][n] = make_float4(r, r, r, r);
    }
    grid_bar(++barK);   // edges + partition + state all visible now

    // ---- Stage this CTA's packed edge slice into shared memory ----
    const int rowA_cta = g_rowLo[bid * QPC];
    const int rowB_cta = g_rowLo[(bid + 1) * QPC];
    const int ebase    = g_rowptr[rowA_cta];
    const int ecnt     = g_rowptr[rowB_cta] - ebase;
    const bool fits    = (ecnt <= ECAP);
    if (fits) {
        for (int i = tid; i < ecnt; i += NTHREADS)
            s_ws[i] = g_wp[ebase + i];
    }
    __syncthreads();

    const int q    = tid & 3;
    const int qid  = gtid >> 2;
    const int rowA = g_rowLo[qid];
    const int rowB = g_rowLo[qid + 1];
    const unsigned qmask = 0xFu << (tid & 28);

    if (!fits) {
        run_steps_fallback(rowA, rowB, q, qmask, x, out, cbase, chunk, tid, barK);
        return;
    }

    // ---- Hot loop: 50 steps; scattered out-stores replaced by coalesced epilogue copy ----
    for (int t = 0; t < T_STEPS; t++) {
        const float4* __restrict__ Rc  = g_R[t & 1];
        float*        __restrict__ Rnf = (float*)(g_R[(t + 1) & 1]);
        const float*  __restrict__ xt  = x + t * N_NODES;

        // Coalesced emission of the PREVIOUS step's output (Rc is stable this phase;
        // it is not overwritten until step t+1, which is behind the next barrier).
        if (t > 0) copy_plane(t - 1, Rc, out, cbase, chunk, tid);

        for (int r = rowA; r < rowB; ++r) {
            const int beg = g_rowptr[r];          // L1-hit (same addr each step)
            const int end = g_rowptr[r + 1];
            const float xv = __ldcg(xt + q * TN + r);

            unsigned long long a01 = 0ull, a23 = 0ull;   // f32x2 accumulators
#pragma unroll 4
            for (int e = beg + q; e < end; e += 4) {
                unsigned u = s_ws[e - ebase];     // LDS.32 (1 wavefront)
                float w = __half2float(__ushort_as_half((unsigned short)(u & 0xFFFFu)));
                unsigned long long w2, r01, r23;
                asm("mov.b64 %0, {%1, %1};" : "=l"(w2) : "f"(w));
                asm volatile("ld.global.cg.v2.b64 {%0, %1}, [%2];"
                             : "=l"(r01), "=l"(r23) : "l"(Rc + (u >> 16)));
                asm("fma.rn.f32x2 %0, %1, %2, %3;" : "=l"(a01) : "l"(w2), "l"(r01), "l"(a01));
                asm("fma.rn.f32x2 %0, %1, %2, %3;" : "=l"(a23) : "l"(w2), "l"(r23), "l"(a23));
            }
            // quad reduction with quad-local mask (quads diverge; quad lanes don't)
#pragma unroll
            for (int off = 1; off < 4; off <<= 1) {
                unsigned long long b01 = __shfl_xor_sync(qmask, a01, off);
                unsigned long long b23 = __shfl_xor_sync(qmask, a23, off);
                asm("add.rn.f32x2 %0, %1, %2;" : "=l"(a01) : "l"(a01), "l"(b01));
                asm("add.rn.f32x2 %0, %1, %2;" : "=l"(a23) : "l"(a23), "l"(b23));
            }
            unsigned long long sel = (q < 2) ? a01 : a23;
            float lo, hi;
            asm("mov.b64 {%0, %1}, %2;" : "=f"(lo), "=f"(hi) : "l"(sel));
            float acc = (q & 1) ? hi : lo;

            float2 ab = g_ab[r];                  // L1-hit
            float  v  = g_Vf[4 * r + q];          // L1-hit
            v = fmaf(ab.x, (ab.y - v) + (acc + xv), v);
            g_Vf[4 * r + q] = v;
            Rnf[4 * r + q] = fmaxf(v, 0.0f);      // quad-coalesced 16B
        }
        if (t != T_STEPS - 1) grid_bar(++barK);
    }

    // Final plane: rates of step T-1 live in g_R[T_STEPS & 1]; sync, then emit.
    grid_bar(++barK);
    copy_plane(T_STEPS - 1, g_R[T_STEPS & 1], out, cbase, chunk, tid);
}

extern "C" void kernel_launch(void* const* d_in, const int* in_sizes, int n_in,
                              void* d_out, int out_size) {
    const float* x      = (const float*)d_in[0];
    const float* bias   = (const float*)d_in[1];
    const float* tconst = (const float*)d_in[2];
    const float* sign   = (const float*)d_in[3];
    const float* cnt    = (const float*)d_in[4];
    const float* strg   = (const float*)d_in[5];
    const int*   src    = (const int*)d_in[6];
    const int*   tgt    = (const int*)d_in[7];
    float*       out    = (float*)d_out;

    // Attribute query only (no alloc, no sync) -- capture-safe, deterministic.
    int nsm = 148;
    cudaDeviceGetAttribute(&nsm, cudaDevAttrMultiProcessorCount, 0);
    int ncta = nsm * 3;
    if (ncta > MAXCTA) ncta = MAXCTA;
    int chunk = (N_NODES + ncta - 1) / ncta;

    init_kernel<<<128, 512>>>();
    net_kernel<<<ncta, NTHREADS>>>(x, bias, tconst, sign, cnt, strg, src, tgt, out, chunk);
}